// round 1
// baseline (speedup 1.0000x reference)
#include <cuda_runtime.h>
#include <math_constants.h>

#define Bn 4
#define Tn 2048
#define Cn 1024
#define Hn 16
#define Dn 64
#define BT (Bn*Tn)      // 8192
#define NTILES (Tn/64)  // 32

// Scratch (device globals — no allocation allowed)
__device__ float g_q[Bn*Hn*Tn*Dn];   // [bh, t, d]
__device__ float g_k[Bn*Hn*Tn*Dn];
__device__ float g_v[Bn*Hn*Tn*Dn];
__device__ float g_y[BT*Cn];         // [b*T+t, C]  (attention output, pre-proj)

// ---------------------------------------------------------------------------
// SGEMM: C[M,N] = A[M,K] @ W[K,N] + bias  (M=8192, N=K=1024)
// 128x128 tile, BK=8, 256 threads, 8x8 per thread.
// REMAP=true  -> store to [B,H,T,D] layout (for q/k/v)
// REMAP=false -> store row-major [M,N]
// ---------------------------------------------------------------------------
template<bool REMAP>
__device__ __forceinline__ void gemm_body(
    const float* __restrict__ A, const float* __restrict__ W,
    const float* __restrict__ bias, float* __restrict__ out)
{
    __shared__ float As[8][128];   // [k][m]
    __shared__ float Bs[8][128];   // [k][n]

    const int tid = threadIdx.x;
    const int bm = blockIdx.y, bn = blockIdx.x;

    const int aRow = tid >> 1;            // 0..127
    const int aCol = (tid & 1) << 2;      // 0 or 4
    const int bRow = tid >> 5;            // 0..7
    const int bCol = (tid & 31) << 2;     // 0..124

    const int rowBase = (tid >> 4) << 3;  // 0..120
    const int colBase = (tid & 15) << 3;  // 0..120

    float acc[8][8];
    #pragma unroll
    for (int i = 0; i < 8; i++)
        #pragma unroll
        for (int j = 0; j < 8; j++) acc[i][j] = 0.f;

    const float* Aptr = A + (size_t)(bm * 128 + aRow) * 1024 + aCol;
    const float* Wptr = W + (size_t)bRow * 1024 + bn * 128 + bCol;

    for (int kt = 0; kt < 128; kt++) {
        float4 av = *(const float4*)(Aptr + kt * 8);
        float4 bv = *(const float4*)(Wptr + (size_t)kt * 8 * 1024);
        As[aCol + 0][aRow] = av.x;
        As[aCol + 1][aRow] = av.y;
        As[aCol + 2][aRow] = av.z;
        As[aCol + 3][aRow] = av.w;
        *(float4*)&Bs[bRow][bCol] = bv;
        __syncthreads();

        #pragma unroll
        for (int kk = 0; kk < 8; kk++) {
            float4 a0 = *(const float4*)&As[kk][rowBase];
            float4 a1 = *(const float4*)&As[kk][rowBase + 4];
            float4 b0 = *(const float4*)&Bs[kk][colBase];
            float4 b1 = *(const float4*)&Bs[kk][colBase + 4];
            float a[8] = {a0.x, a0.y, a0.z, a0.w, a1.x, a1.y, a1.z, a1.w};
            float b[8] = {b0.x, b0.y, b0.z, b0.w, b1.x, b1.y, b1.z, b1.w};
            #pragma unroll
            for (int i = 0; i < 8; i++)
                #pragma unroll
                for (int j = 0; j < 8; j++)
                    acc[i][j] += a[i] * b[j];
        }
        __syncthreads();
    }

    #pragma unroll
    for (int i = 0; i < 8; i++) {
        const int m = bm * 128 + rowBase + i;
        #pragma unroll
        for (int j = 0; j < 8; j++) {
            const int n = bn * 128 + colBase + j;
            const float val = acc[i][j] + bias[n];
            if (REMAP) {
                const int b = m >> 11, t = m & 2047;
                const int h = n >> 6,  d = n & 63;
                out[(((size_t)(b * Hn + h) * Tn) + t) * Dn + d] = val;
            } else {
                out[(size_t)m * 1024 + n] = val;
            }
        }
    }
}

__global__ __launch_bounds__(256) void sgemm_qkv(
    const float* __restrict__ X,
    const float* __restrict__ Wq, const float* __restrict__ bq,
    const float* __restrict__ Wk, const float* __restrict__ bk,
    const float* __restrict__ Wv, const float* __restrict__ bv)
{
    const float* W; const float* bias; float* out;
    if (blockIdx.z == 0)      { W = Wq; bias = bq; out = g_q; }
    else if (blockIdx.z == 1) { W = Wk; bias = bk; out = g_k; }
    else                      { W = Wv; bias = bv; out = g_v; }
    gemm_body<true>(X, W, bias, out);
}

__global__ __launch_bounds__(256) void sgemm_proj(
    const float* __restrict__ Wp, const float* __restrict__ bp,
    float* __restrict__ out)
{
    gemm_body<false>(g_y, Wp, bp, out);
}

// ---------------------------------------------------------------------------
// Attention kernel: one CTA per (bh, 64-query tile). 256 threads.
// Pass 1: online (max, sumexp) over key tiles, shfl-reduced across 16 lanes.
// Pass 2: recompute scores, write normalized att, accumulate att @ V.
// SMEM: Qs/Ks transposed [d][i] stride 66; Vs [j][d], Ps [j][i] stride 66.
// ---------------------------------------------------------------------------
#define SST 66

__device__ __forceinline__ void load_tile_T(float* dst, const float* __restrict__ src, int tid)
{
    const int row = tid >> 4;
    const int d0 = (tid & 15) << 2;
    #pragma unroll
    for (int it = 0; it < 4; it++) {
        const int r = row + it * 16;
        float4 v4 = *(const float4*)(src + (size_t)r * Dn + d0);
        dst[(d0 + 0) * SST + r] = v4.x;
        dst[(d0 + 1) * SST + r] = v4.y;
        dst[(d0 + 2) * SST + r] = v4.z;
        dst[(d0 + 3) * SST + r] = v4.w;
    }
}

__device__ __forceinline__ void load_tile_N(float* dst, const float* __restrict__ src, int tid)
{
    const int row = tid >> 4;
    const int d0 = (tid & 15) << 2;
    #pragma unroll
    for (int it = 0; it < 4; it++) {
        const int r = row + it * 16;
        float4 v4 = *(const float4*)(src + (size_t)r * Dn + d0);
        float* p = dst + r * SST + d0;
        p[0] = v4.x; p[1] = v4.y; p[2] = v4.z; p[3] = v4.w;
    }
}

__device__ __forceinline__ void compute_scores(
    const float* Qs, const float* Ks, int iBase, int jBase, float s[4][4])
{
    #pragma unroll
    for (int r = 0; r < 4; r++)
        #pragma unroll
        for (int c = 0; c < 4; c++) s[r][c] = 0.f;

    #pragma unroll 16
    for (int kk = 0; kk < 64; kk++) {
        const float* qrow = Qs + kk * SST;
        const float* krow = Ks + kk * SST;
        float2 qa = *(const float2*)(qrow + iBase);
        float2 qb = *(const float2*)(qrow + iBase + 2);
        float2 ka = *(const float2*)(krow + jBase);
        float2 kb = *(const float2*)(krow + jBase + 2);
        float a[4] = {qa.x, qa.y, qb.x, qb.y};
        float b[4] = {ka.x, ka.y, kb.x, kb.y};
        #pragma unroll
        for (int r = 0; r < 4; r++)
            #pragma unroll
            for (int c = 0; c < 4; c++)
                s[r][c] += a[r] * b[c];
    }
}

__global__ __launch_bounds__(256) void attn_kernel(float* __restrict__ att)
{
    extern __shared__ float sm[];
    float* Qs = sm;                  // [d][i] 64x66
    float* Ks = sm + 64 * SST;       // [d][j]
    float* Vs = sm + 2 * 64 * SST;   // [j][d]
    float* Ps = sm + 3 * 64 * SST;   // [j][i]

    const int bh = blockIdx.y;
    const int qt = blockIdx.x;
    const int qbase = qt * 64;
    const int tid = threadIdx.x;
    const int iBase = (tid >> 4) << 2;   // query row base (4 rows)
    const int cBase = (tid & 15) << 2;   // key-col / head-dim base (4 cols)

    const float* qp = g_q + ((size_t)bh * Tn + qbase) * Dn;
    const float* kp = g_k + (size_t)bh * Tn * Dn;
    const float* vp = g_v + (size_t)bh * Tn * Dn;
    float* attp = att + ((size_t)bh * Tn + qbase) * Tn;

    load_tile_T(Qs, qp, tid);
    __syncthreads();

    const float scale = 0.125f;  // 1/sqrt(64)

    float m[4], l[4];
    #pragma unroll
    for (int r = 0; r < 4; r++) { m[r] = -CUDART_INF_F; l[r] = 0.f; }

    // ---------------- PASS 1: row max + sumexp ----------------
    for (int kt = 0; kt <= qt; kt++) {
        load_tile_T(Ks, kp + (size_t)kt * 64 * Dn, tid);
        __syncthreads();

        float s[4][4];
        compute_scores(Qs, Ks, iBase, cBase, s);

        const bool diag = (kt == qt);
        #pragma unroll
        for (int r = 0; r < 4; r++) {
            #pragma unroll
            for (int c = 0; c < 4; c++) {
                s[r][c] *= scale;
                if (diag) {
                    const int gi = qbase + iBase + r;
                    const int gj = kt * 64 + cBase + c;
                    if (gj > gi) s[r][c] = -CUDART_INF_F;
                }
            }
            float tm = s[r][0];
            #pragma unroll
            for (int c = 1; c < 4; c++) tm = fmaxf(tm, s[r][c]);
            const float mn = fmaxf(m[r], tm);
            if (mn > -CUDART_INF_F) {
                float sum = 0.f;
                #pragma unroll
                for (int c = 0; c < 4; c++) sum += __expf(s[r][c] - mn);
                l[r] = l[r] * __expf(m[r] - mn) + sum;
                m[r] = mn;
            }
        }
        __syncthreads();
    }

    // reduce (m,l) across the 16 lanes that share the same query rows
    #pragma unroll
    for (int r = 0; r < 4; r++) {
        #pragma unroll
        for (int off = 8; off > 0; off >>= 1) {
            const float om = __shfl_xor_sync(0xffffffffu, m[r], off);
            const float ol = __shfl_xor_sync(0xffffffffu, l[r], off);
            const float mn = fmaxf(m[r], om);
            if (mn > -CUDART_INF_F) {
                l[r] = l[r] * __expf(m[r] - mn) + ol * __expf(om - mn);
                m[r] = mn;
            }
        }
    }
    float invl[4];
    #pragma unroll
    for (int r = 0; r < 4; r++) invl[r] = 1.f / l[r];

    // ---------------- PASS 2: write att + accumulate y ----------------
    float yacc[4][4];
    #pragma unroll
    for (int r = 0; r < 4; r++)
        #pragma unroll
        for (int c = 0; c < 4; c++) yacc[r][c] = 0.f;

    for (int kt = 0; kt < NTILES; kt++) {
        if (kt <= qt) {
            __syncthreads();  // guard Ks/Vs/Ps reuse from previous iter
            load_tile_T(Ks, kp + (size_t)kt * 64 * Dn, tid);
            load_tile_N(Vs, vp + (size_t)kt * 64 * Dn, tid);
            __syncthreads();

            float s[4][4];
            compute_scores(Qs, Ks, iBase, cBase, s);

            const bool diag = (kt == qt);
            float p[4][4];
            #pragma unroll
            for (int r = 0; r < 4; r++) {
                #pragma unroll
                for (int c = 0; c < 4; c++) {
                    bool valid = true;
                    if (diag) {
                        const int gi = qbase + iBase + r;
                        const int gj = kt * 64 + cBase + c;
                        valid = (gj <= gi);
                    }
                    p[r][c] = valid ? __expf(s[r][c] * scale - m[r]) * invl[r] : 0.f;
                }
                // coalesced att write
                float4 pv = make_float4(p[r][0], p[r][1], p[r][2], p[r][3]);
                *(float4*)(attp + (size_t)(iBase + r) * Tn + kt * 64 + cBase) = pv;
                // transposed P for AV
                #pragma unroll
                for (int c = 0; c < 4; c++)
                    Ps[(cBase + c) * SST + iBase + r] = p[r][c];
            }
            __syncthreads();

            #pragma unroll 16
            for (int j = 0; j < 64; j++) {
                const float* prow = Ps + j * SST;
                const float* vrow = Vs + j * SST;
                float2 pa = *(const float2*)(prow + iBase);
                float2 pb = *(const float2*)(prow + iBase + 2);
                float2 va = *(const float2*)(vrow + cBase);
                float2 vb = *(const float2*)(vrow + cBase + 2);
                float pr[4] = {pa.x, pa.y, pb.x, pb.y};
                float vv[4] = {va.x, va.y, vb.x, vb.y};
                #pragma unroll
                for (int r = 0; r < 4; r++)
                    #pragma unroll
                    for (int c = 0; c < 4; c++)
                        yacc[r][c] += pr[r] * vv[c];
            }
        } else {
            // strict upper triangle: att must be exactly 0 (d_out is poisoned)
            const float4 z = make_float4(0.f, 0.f, 0.f, 0.f);
            #pragma unroll
            for (int r = 0; r < 4; r++)
                *(float4*)(attp + (size_t)(iBase + r) * Tn + kt * 64 + cBase) = z;
        }
    }

    // write y tile to [b*T+t, C] layout for the output projection
    const int b = bh >> 4, h = bh & 15;
    #pragma unroll
    for (int r = 0; r < 4; r++) {
        const int t = qbase + iBase + r;
        float4 yv = make_float4(yacc[r][0], yacc[r][1], yacc[r][2], yacc[r][3]);
        *(float4*)(g_y + ((size_t)(b * Tn + t)) * Cn + h * Dn + cBase) = yv;
    }
}

// ---------------------------------------------------------------------------
extern "C" void kernel_launch(void* const* d_in, const int* in_sizes, int n_in,
                              void* d_out, int out_size)
{
    const float* x  = (const float*)d_in[0];
    const float* Wq = (const float*)d_in[1];
    const float* bq = (const float*)d_in[2];
    const float* Wk = (const float*)d_in[3];
    const float* bk = (const float*)d_in[4];
    const float* Wv = (const float*)d_in[5];
    const float* bv = (const float*)d_in[6];
    const float* Wp = (const float*)d_in[7];
    const float* bp = (const float*)d_in[8];

    float* y_out   = (float*)d_out;                       // [B,T,C]
    float* att_out = y_out + (size_t)BT * Cn;             // [B,H,T,T]

    // QKV projections (z selects q/k/v)
    sgemm_qkv<<<dim3(8, 64, 3), 256>>>(x, Wq, bq, Wk, bk, Wv, bv);

    // Fused attention (scores -> softmax -> att write -> att@V)
    const int smem = 4 * 64 * SST * (int)sizeof(float);   // 67584 B
    cudaFuncSetAttribute(attn_kernel, cudaFuncAttributeMaxDynamicSharedMemorySize, smem);
    attn_kernel<<<dim3(NTILES, Bn * Hn), 256, smem>>>(att_out);

    // Output projection
    sgemm_proj<<<dim3(8, 64), 256>>>(Wp, bp, y_out);
}